// round 17
// baseline (speedup 1.0000x reference)
#include <cuda_runtime.h>

#define NODES  8448
#define NB     10
#define ITERS  5
#define TPB    768
#define NPT    11            // 768 * 11 = 8448 exact — no guards, no tail
#define NPTDB  7             // nodes i<7 (n<5376) are double-buffered
#define DBN    (NPTDB * TPB) // 5376
#define NBATCH 1024
#define RPC    4             // batch rows per CTA (packed as float4)
#define NGROUPS (NBATCH / RPC)   // 256
#define NQG    (NODES / 8)   // 1056 quarter-warp node groups

// float4 main table (8448) + float4 alt slots for DB nodes (5376) = 221184 B
#define SMEM_BYTES ((NODES + DBN) * 16)

// Global scratch (static __device__ arrays; no allocation).
// Pre-resolved BYTE offsets into the smem table, one row of 12 u32 per node
// (10 used + 2 pad for 16B alignment). Even parity: idx*16. Odd parity:
// (idx + NODES)*16 for double-buffered neighbors (idx < DBN), idx*16 otherwise.
__device__ __align__(16) unsigned g_offe[NODES][12];
__device__ __align__(16) unsigned g_offo[NODES][12];
__device__ float2       g_wr[NODES];          // packed (w_res[0][n], w_res[1][n])
__device__ float4       g_wllr[NGROUPS][NODES];
__device__ float4       g_P[NGROUPS][NODES];  // vm_{t-1}

// ---------------------------------------------------------------------------
// Prep: one warp per 8-node group; threads 0..9 own slot counters; argmin over
// slots via a single __reduce_min_sync (bit-identical schedule to R7 greedy).
// Each slot-lane then writes its FINAL byte offsets for both parities.
__global__ void prep_sched_kernel(const int* __restrict__ check_idx,
                                  const float* __restrict__ w_res)
{
    const int warp = (blockIdx.x * blockDim.x + threadIdx.x) >> 5;
    const int lane = threadIdx.x & 31;
    if (warp >= NQG) return;

    const int base = warp * 80;          // 8 nodes * 10 indices
    const unsigned v0 = (unsigned)check_idx[base + lane];
    const unsigned v1 = (unsigned)check_idx[base + 32 + lane];
    const unsigned v2 = (lane < 16) ? (unsigned)check_idx[base + 64 + lane] : 0u;

    if (lane < 8) {
        const int n = warp * 8 + lane;
        g_wr[n] = make_float2(w_res[n], w_res[NODES + n]);
    }

    const bool is_slot = (lane < 10);
    unsigned cnt = 0u;                   // my slot's 8 nibble bank-group counts

    #pragma unroll
    for (int ln = 0; ln < 8; ln++) {
        unsigned taken = 0u;
        unsigned perm  = 0u;

        #pragma unroll
        for (int j = 0; j < 10; j++) {
            const int flat = ln * 10 + j;          // compile-time constant
            unsigned v;
            if      (flat < 32) v = __shfl_sync(0xFFFFFFFFu, v0, flat);
            else if (flat < 64) v = __shfl_sync(0xFFFFFFFFu, v1, flat - 32);
            else                v = __shfl_sync(0xFFFFFFFFu, v2, flat - 64);

            const unsigned sh = (v & 7u) * 4u;
            const unsigned c  = (cnt >> sh) & 0xFu;
            const unsigned key = (is_slot && !taken) ? ((c << 8) | (unsigned)lane)
                                                     : 0xFFFFu;
            const unsigned best = __reduce_min_sync(0xFFFFFFFFu, key) & 0xFFu;
            if ((unsigned)lane == best) {
                taken = 1u;
                cnt  += 1u << sh;
                perm  = v;
            }
        }
        // lanes 0..9 each own one slot's value -> write final byte offsets
        if (is_slot) {
            const int n = warp * 8 + ln;
            const unsigned offE = perm * 16u;
            const unsigned idxO = perm + ((perm < (unsigned)DBN) ? (unsigned)NODES : 0u);
            g_offe[n][lane] = offE;
            g_offo[n][lane] = idxO * 16u;
        }
    }
}

// ---------------------------------------------------------------------------
// Fast 2*atanh (MUFU rcp+lg2; rel err ~3e-6 — proven in R14).
__device__ __forceinline__ float fast_2atanh(float p)
{
    p = fminf(0.999999f, fmaxf(-0.999999f, p));
    return __logf(__fdividef(1.0f + p, 1.0f - p));
}

__device__ __forceinline__ float4 ld4(const char* stb, unsigned off)
{
    return *reinterpret_cast<const float4*>(stb + off);
}

// One node's Phase-B body (gather + product + 2*atanh + residual update).
// Multiply order identical to R16: (s0*s2*s4*s6*s8) * (s1*s3*s5*s7*s9).
__device__ __forceinline__ float4 node_update(
    const char* __restrict__ stb,
    const uint4 oA, const uint4 oB, const uint2 oC,
    const float4 wl, const float2 wr, const float4 pr, const float4 c,
    bool use_prev)
{
    float4 p0 = ld4(stb, oA.x);          // s0
    float4 p1 = ld4(stb, oA.y);          // s1
    {
        const float4 a = ld4(stb, oA.z); // s2
        const float4 b = ld4(stb, oA.w); // s3
        p0.x *= a.x; p0.y *= a.y; p0.z *= a.z; p0.w *= a.w;
        p1.x *= b.x; p1.y *= b.y; p1.z *= b.z; p1.w *= b.w;
    }
    {
        const float4 a = ld4(stb, oB.x); // s4
        const float4 b = ld4(stb, oB.y); // s5
        p0.x *= a.x; p0.y *= a.y; p0.z *= a.z; p0.w *= a.w;
        p1.x *= b.x; p1.y *= b.y; p1.z *= b.z; p1.w *= b.w;
    }
    {
        const float4 a = ld4(stb, oB.z); // s6
        const float4 b = ld4(stb, oB.w); // s7
        p0.x *= a.x; p0.y *= a.y; p0.z *= a.z; p0.w *= a.w;
        p1.x *= b.x; p1.y *= b.y; p1.z *= b.z; p1.w *= b.w;
    }
    {
        const float4 a = ld4(stb, oC.x); // s8
        const float4 b = ld4(stb, oC.y); // s9
        p0.x *= a.x; p0.y *= a.y; p0.z *= a.z; p0.w *= a.w;
        p1.x *= b.x; p1.y *= b.y; p1.z *= b.z; p1.w *= b.w;
    }
    float4 p;
    p.x = p0.x * p1.x;  p.y = p0.y * p1.y;
    p.z = p0.z * p1.z;  p.w = p0.w * p1.w;

    float4 nv;
    nv.x = wl.x + fast_2atanh(p.x) + wr.x * c.x;
    nv.y = wl.y + fast_2atanh(p.y) + wr.x * c.y;
    nv.z = wl.z + fast_2atanh(p.z) + wr.x * c.z;
    nv.w = wl.w + fast_2atanh(p.w) + wr.x * c.w;
    if (use_prev) {
        nv.x += wr.y * pr.x;  nv.y += wr.y * pr.y;
        nv.z += wr.y * pr.z;  nv.w += wr.y * pr.w;
    }
    return nv;
}

// ---------------------------------------------------------------------------
__global__ __launch_bounds__(TPB, 1)
void ldpc4_kernel(const float* __restrict__ input_llr,
                  const float* __restrict__ w_ch,
                  float*       __restrict__ out)
{
    extern __shared__ float4 st[];   // [0,NODES): main slots; [NODES,NODES+DBN): alt
    const char* stb = reinterpret_cast<const char*>(st);
    const int tid  = threadIdx.x;
    const int g    = blockIdx.x;
    const int row0 = g * RPC;
    const float* llr0 = input_llr + (size_t)row0 * NODES;

    float4 cur[NPT];   // current var_messages for this thread's nodes (4 rows)

    // Prologue: weighted LLR -> registers + global scratch; initial tanh -> main.
    #pragma unroll
    for (int i = 0; i < NPT; i++) {
        const int n = tid + i * TPB;
        const float wc = w_ch[n];
        float4 wl;
        wl.x = llr0[n]             * wc;
        wl.y = llr0[NODES + n]     * wc;
        wl.z = llr0[2 * NODES + n] * wc;
        wl.w = llr0[3 * NODES + n] * wc;
        g_wllr[g][n] = wl;
        cur[i] = wl;
        float4 t;
        t.x = tanhf(0.5f * wl.x);
        t.y = tanhf(0.5f * wl.y);
        t.z = tanhf(0.5f * wl.z);
        t.w = tanhf(0.5f * wl.w);
        st[n] = t;
    }
    __syncthreads();

    #pragma unroll 1
    for (int it = 0; it < ITERS; it++) {
        const unsigned (*__restrict__ off)[12] = (it & 1) ? g_offo : g_offe;
        float4* __restrict__ dbw = (it & 1) ? st : (st + NODES);  // alt slots t+1
        const bool more = (it < ITERS - 1);

        // Phase B (DB nodes, i<7): gather/update, then FUSED tanh for next
        // iteration stored to the alternate slot (no barrier needed).
        #pragma unroll 2
        for (int i = 0; i < NPTDB; i++) {
            const int n = tid + i * TPB;
            const uint4 oA = *reinterpret_cast<const uint4*>(&off[n][0]);
            const uint4 oB = *reinterpret_cast<const uint4*>(&off[n][4]);
            const uint2 oC = *reinterpret_cast<const uint2*>(&off[n][8]);
            float4 pr = make_float4(0.f, 0.f, 0.f, 0.f);
            if (it > 0) pr = g_P[g][n];
            const float4 nv = node_update(stb, oA, oB, oC,
                                          g_wllr[g][n], g_wr[n], pr, cur[i], it > 0);
            if (more) g_P[g][n] = cur[i];
            cur[i] = nv;
            if (more) {
                float4 t;
                t.x = tanhf(0.5f * nv.x);
                t.y = tanhf(0.5f * nv.y);
                t.z = tanhf(0.5f * nv.z);
                t.w = tanhf(0.5f * nv.w);
                dbw[n] = t;
            }
        }

        // Phase B (tail nodes, i>=7): gather/update only.
        #pragma unroll 2
        for (int i = NPTDB; i < NPT; i++) {
            const int n = tid + i * TPB;
            const uint4 oA = *reinterpret_cast<const uint4*>(&off[n][0]);
            const uint4 oB = *reinterpret_cast<const uint4*>(&off[n][4]);
            const uint2 oC = *reinterpret_cast<const uint2*>(&off[n][8]);
            float4 pr = make_float4(0.f, 0.f, 0.f, 0.f);
            if (it > 0) pr = g_P[g][n];
            const float4 nv = node_update(stb, oA, oB, oC,
                                          g_wllr[g][n], g_wr[n], pr, cur[i], it > 0);
            if (more) g_P[g][n] = cur[i];
            cur[i] = nv;
        }
        __syncthreads();   // all reads of this iteration's table complete

        if (more) {
            // Serial Phase A only for the non-double-buffered tail (4/11).
            #pragma unroll
            for (int i = NPTDB; i < NPT; i++) {
                const int n = tid + i * TPB;
                const float4 v = cur[i];
                float4 t;
                t.x = tanhf(0.5f * v.x);
                t.y = tanhf(0.5f * v.y);
                t.z = tanhf(0.5f * v.z);
                t.w = tanhf(0.5f * v.w);
                st[n] = t;     // main slot (read by both parities)
            }
            __syncthreads();
        }
    }

    // Epilogue: soft_bits = sigmoid(vm + input_llr), 4 coalesced row streams.
    #pragma unroll
    for (int i = 0; i < NPT; i++) {
        const int n = tid + i * TPB;
        const float4 c = cur[i];
        float* o = out + (size_t)row0 * NODES;
        const float zx = c.x + llr0[n];
        const float zy = c.y + llr0[NODES + n];
        const float zz = c.z + llr0[2 * NODES + n];
        const float zw = c.w + llr0[3 * NODES + n];
        o[n]             = 1.0f / (1.0f + expf(-zx));
        o[NODES + n]     = 1.0f / (1.0f + expf(-zy));
        o[2 * NODES + n] = 1.0f / (1.0f + expf(-zz));
        o[3 * NODES + n] = 1.0f / (1.0f + expf(-zw));
    }
}

// ---------------------------------------------------------------------------
extern "C" void kernel_launch(void* const* d_in, const int* in_sizes, int n_in,
                              void* d_out, int out_size)
{
    const float* input_llr = (const float*)d_in[0];
    const float* w_ch      = (const float*)d_in[1];
    const float* w_res     = (const float*)d_in[2];
    const int*   check_idx = (const int*)d_in[3];
    // d_in[4] (var_index_tensor) is unused by the reference computation.
    float* out = (float*)d_out;

    // one warp per group: NQG * 32 threads
    prep_sched_kernel<<<(NQG * 32 + 255) / 256, 256>>>(check_idx, w_res);

    cudaFuncSetAttribute(ldpc4_kernel,
                         cudaFuncAttributeMaxDynamicSharedMemorySize, SMEM_BYTES);
    ldpc4_kernel<<<NGROUPS, TPB, SMEM_BYTES>>>(input_llr, w_ch, out);
}